// round 14
// baseline (speedup 1.0000x reference)
#include <cuda_runtime.h>
#include <cuda_fp16.h>

#define N_NODES_C 100000
#define N_EDGES_C 50000
#define NNZ_CAP   1600000
#define F1 128
#define F2 16
#define NB_E ((N_EDGES_C + 511) / 512)   // 98
#define NB_N ((N_NODES_C + 511) / 512)   // 196

// ---------------- static scratch (no cudaMalloc anywhere) ----------------
__device__ int   g_idx64;
__device__ int   g_ncnt[N_NODES_C];      // zero at load; re-zeroed by tail kernel each run
__device__ int   g_ecnt[N_EDGES_C];
__device__ int   g_noff[N_NODES_C + 1];
__device__ int   g_eoff[N_EDGES_C + 1];
__device__ int   g_bse[NB_E];
__device__ int   g_bsn[NB_N];
__device__ float g_dinv[N_NODES_C];
__device__ float g_binv[N_EDGES_C];
__device__ int   g_ni32[NNZ_CAP];
__device__ int   g_ei32[NNZ_CAP];
__device__ int   g_rank_n[NNZ_CAP];
__device__ int   g_rank_e[NNZ_CAP];
__device__ int   g_e_members[NNZ_CAP];
__device__ int   g_n_members[NNZ_CAP];
__device__ __align__(16) __half g_w1h[F1 * F1];
__device__ __align__(16) __half g_w1l[F1 * F1];
__device__ __align__(16) __half g_xw[(size_t)N_NODES_C * F1];
__device__ __align__(16) __half g_ef[(size_t)N_EDGES_C * F1];
__device__ __align__(16) __half g_hw[(size_t)N_NODES_C * F2];
__device__ __align__(16) __half g_ef2[(size_t)N_EDGES_C * F2];

__device__ __forceinline__ int load_idx(const void* p, int i, int is64) {
    return is64 ? (int)((const long long*)p)[i] : ((const int*)p)[i];
}

// ---------------- tiny detect (counters zeroed by tail kernel / static init) -----
__global__ void detect_kernel(const void* ni, int nnz) {
    __shared__ int bad_s;
    if (threadIdx.x == 0) bad_s = 0;
    __syncthreads();
    int k = nnz < 64 ? nnz : 64;
    if ((int)threadIdx.x < k) {
        long long v = ((const long long*)ni)[threadIdx.x];
        if (v < 0 || v >= (1LL << 31)) atomicOr(&bad_s, 1);
    }
    __syncthreads();
    if (threadIdx.x == 0) g_idx64 = bad_s ? 0 : 1;
}

// ---------------- tail: re-zero counters for the next run/replay ----------------
__global__ void zero_tail_kernel() {
    int i = blockIdx.x * blockDim.x + threadIdx.x;
    int4 z = make_int4(0, 0, 0, 0);
    if (i < N_NODES_C / 4) ((int4*)g_ncnt)[i] = z;
    if (i < N_EDGES_C / 4) ((int4*)g_ecnt)[i] = z;
}

// ---------------- W1 -> fp16 hi/lo, transposed (s2) ----------------
__global__ void split_w1_kernel(const float* __restrict__ W) {
    int i = blockIdx.x * blockDim.x + threadIdx.x;
    if (i < F1 * F1) {
        int k = i >> 7, n = i & 127;
        float w = W[i];
        __half hi = __float2half_rn(w);
        __half lo = __float2half_rn(w - __half2float(hi));
        g_w1h[n * F1 + k] = hi;
        g_w1l[n * F1 + k] = lo;
    }
}

// ---------------- per-side CSR kernels, 4 incidences per thread ----------------
__global__ void hist_side_kernel(const void* idx, int* __restrict__ idx32,
                                 int* __restrict__ rank, int* __restrict__ cnt, int nnz) {
    int i0 = (blockIdx.x * blockDim.x + threadIdx.x) * 4;
    if (i0 >= nnz) return;
    int is64 = g_idx64;
    if (i0 + 3 < nnz) {
        int v[4];
        if (is64) {
            longlong2 a = *(const longlong2*)((const long long*)idx + i0);
            longlong2 b = *(const longlong2*)((const long long*)idx + i0 + 2);
            v[0] = (int)a.x; v[1] = (int)a.y; v[2] = (int)b.x; v[3] = (int)b.y;
        } else {
            int4 a = *(const int4*)((const int*)idx + i0);
            v[0] = a.x; v[1] = a.y; v[2] = a.z; v[3] = a.w;
        }
        int r[4];
#pragma unroll
        for (int k = 0; k < 4; k++) r[k] = atomicAdd(&cnt[v[k]], 1);
        *(int4*)(idx32 + i0) = make_int4(v[0], v[1], v[2], v[3]);
        *(int4*)(rank + i0)  = make_int4(r[0], r[1], r[2], r[3]);
    } else {
        for (int k = 0; k < 4 && i0 + k < nnz; k++) {
            int v = load_idx(idx, i0 + k, is64);
            idx32[i0 + k] = v;
            rank[i0 + k]  = atomicAdd(&cnt[v], 1);
        }
    }
}

__global__ __launch_bounds__(512) void bsums_side_kernel(const int* __restrict__ cnt,
                                                         int n, int* __restrict__ bs) {
    __shared__ int s[512];
    int i = blockIdx.x * 512 + threadIdx.x;
    s[threadIdx.x] = (i < n) ? cnt[i] : 0;
    __syncthreads();
    for (int d = 256; d > 0; d >>= 1) {
        if ((int)threadIdx.x < d) s[threadIdx.x] += s[threadIdx.x + d];
        __syncthreads();
    }
    if (threadIdx.x == 0) bs[blockIdx.x] = s[0];
}

// apply with inline base computation (no separate scanmid launch)
__global__ __launch_bounds__(512) void apply_side_kernel(const int* __restrict__ cnt, int n,
                                                         const int* __restrict__ bsraw,
                                                         int* __restrict__ off,
                                                         float* __restrict__ inv) {
    __shared__ int s[512];
    __shared__ int wsum[16];
    __shared__ int base_s;
    const int tid = threadIdx.x, b = blockIdx.x;

    int part = (tid < b) ? bsraw[tid] : 0;
    for (int d = 16; d > 0; d >>= 1) part += __shfl_down_sync(0xffffffffu, part, d);
    if ((tid & 31) == 0) wsum[tid >> 5] = part;
    __syncthreads();
    if (tid == 0) {
        int t = 0;
#pragma unroll
        for (int i = 0; i < 16; i++) t += wsum[i];
        base_s = t;
    }
    __syncthreads();

    int i = b * 512 + tid;
    int v = (i < n) ? cnt[i] : 0;
    s[tid] = v;
    __syncthreads();
    for (int d = 1; d < 512; d <<= 1) {
        int t = (tid >= d) ? s[tid - d] : 0;
        __syncthreads();
        s[tid] += t;
        __syncthreads();
    }
    int base = base_s;
    if (i < n) {
        off[i] = base + s[tid] - v;
        inv[i] = v > 0 ? 1.f / (float)v : 0.f;
        if (i == n - 1) off[n] = base + s[tid];
    }
}

// atomic-free fill, 4 per thread
__global__ void fill_side_kernel(const int* __restrict__ idx32, const int* __restrict__ rank,
                                 const int* __restrict__ off, const void* other,
                                 int* __restrict__ members, int nnz) {
    int i0 = (blockIdx.x * blockDim.x + threadIdx.x) * 4;
    if (i0 >= nnz) return;
    int is64 = g_idx64;
    if (i0 + 3 < nnz) {
        int4 id = *(const int4*)(idx32 + i0);
        int4 rk = *(const int4*)(rank + i0);
        int ov[4];
        if (is64) {
            longlong2 a = *(const longlong2*)((const long long*)other + i0);
            longlong2 b = *(const longlong2*)((const long long*)other + i0 + 2);
            ov[0] = (int)a.x; ov[1] = (int)a.y; ov[2] = (int)b.x; ov[3] = (int)b.y;
        } else {
            int4 a = *(const int4*)((const int*)other + i0);
            ov[0] = a.x; ov[1] = a.y; ov[2] = a.z; ov[3] = a.w;
        }
        int o0 = off[id.x], o1 = off[id.y], o2 = off[id.z], o3 = off[id.w];
        members[o0 + rk.x] = ov[0];
        members[o1 + rk.y] = ov[1];
        members[o2 + rk.z] = ov[2];
        members[o3 + rk.w] = ov[3];
    } else {
        for (int k = 0; k < 4 && i0 + k < nnz; k++)
            members[off[idx32[i0 + k]] + rank[i0 + k]] = load_idx(other, i0 + k, is64);
    }
}

// ---------------- node-level GEMM (fp16 2-pass mma) ----------------
__device__ __forceinline__ void mma_f16(float* c, unsigned a0, unsigned a1,
                                        unsigned a2, unsigned a3,
                                        unsigned b0, unsigned b1) {
    asm("mma.sync.aligned.m16n8k16.row.col.f32.f16.f16.f32 "
        "{%0,%1,%2,%3}, {%4,%5,%6,%7}, {%8,%9}, {%0,%1,%2,%3};"
        : "+f"(c[0]), "+f"(c[1]), "+f"(c[2]), "+f"(c[3])
        : "r"(a0), "r"(a1), "r"(a2), "r"(a3), "r"(b0), "r"(b1));
}

__global__ __launch_bounds__(512) void gemm1_f16(const float* __restrict__ A,
                                                 __half* __restrict__ out, int M) {
    __shared__ __half As[128][40];
    __shared__ __half Bh[128][40];
    __shared__ __half Bl[128][40];
    const int tid = threadIdx.x;
    const int wid = tid >> 5, lane = tid & 31;
    const int g = lane >> 2, t = lane & 3;
    const int wm = (wid >> 2) * 32, wn = (wid & 3) * 32;
    const int mbase = blockIdx.x * 128;

    float acc[2][4][4];
#pragma unroll
    for (int a = 0; a < 2; a++)
#pragma unroll
        for (int b = 0; b < 4; b++)
#pragma unroll
            for (int c = 0; c < 4; c++) acc[a][b][c] = 0.f;

    for (int kc = 0; kc < 128; kc += 32) {
#pragma unroll
        for (int i = 0; i < 2; i++) {
            int idx = tid + i * 512;
            int r = idx >> 3, q = idx & 7;
            int row = mbase + r;
            float4 v = (row < M) ? *(const float4*)&A[(size_t)row * 128 + kc + q * 4]
                                 : make_float4(0.f, 0.f, 0.f, 0.f);
            uint2 h;
            *(__half2*)&h.x = __floats2half2_rn(v.x, v.y);
            *(__half2*)&h.y = __floats2half2_rn(v.z, v.w);
            *(uint2*)&As[r][q * 4] = h;
            *(uint2*)&Bh[r][q * 4] = *(const uint2*)&g_w1h[r * 128 + kc + q * 4];
            *(uint2*)&Bl[r][q * 4] = *(const uint2*)&g_w1l[r * 128 + kc + q * 4];
        }
        __syncthreads();

#pragma unroll
        for (int ks = 0; ks < 2; ks++) {
            const int k0 = ks * 16;
#pragma unroll
            for (int mt = 0; mt < 2; mt++) {
                const int rm = wm + mt * 16;
                unsigned a0 = *(unsigned*)&As[rm + g][k0 + 2 * t];
                unsigned a1 = *(unsigned*)&As[rm + g + 8][k0 + 2 * t];
                unsigned a2 = *(unsigned*)&As[rm + g][k0 + 2 * t + 8];
                unsigned a3 = *(unsigned*)&As[rm + g + 8][k0 + 2 * t + 8];
#pragma unroll
                for (int nt = 0; nt < 4; nt++) {
                    int n = wn + nt * 8 + g;
                    unsigned bh0 = *(unsigned*)&Bh[n][k0 + 2 * t];
                    unsigned bh1 = *(unsigned*)&Bh[n][k0 + 2 * t + 8];
                    unsigned bl0 = *(unsigned*)&Bl[n][k0 + 2 * t];
                    unsigned bl1 = *(unsigned*)&Bl[n][k0 + 2 * t + 8];
                    mma_f16(acc[mt][nt], a0, a1, a2, a3, bh0, bh1);
                    mma_f16(acc[mt][nt], a0, a1, a2, a3, bl0, bl1);
                }
            }
        }
        __syncthreads();
    }

#pragma unroll
    for (int mt = 0; mt < 2; mt++) {
#pragma unroll
        for (int nt = 0; nt < 4; nt++) {
            int row = mbase + wm + mt * 16 + g;
            int col = wn + nt * 8 + 2 * t;
            if (row < M)
                *(__half2*)&out[(size_t)row * 128 + col] =
                    __floats2half2_rn(acc[mt][nt][0], acc[mt][nt][1]);
            if (row + 8 < M)
                *(__half2*)&out[(size_t)(row + 8) * 128 + col] =
                    __floats2half2_rn(acc[mt][nt][2], acc[mt][nt][3]);
        }
    }
}

// ---------------- gather-reduce F=128 fp16 (warp per row, 8-deep MLP) -------------
__device__ __forceinline__ void acc_h4(float4& a, uint2 raw) {
    float2 f01 = __half22float2(*(__half2*)&raw.x);
    float2 f23 = __half22float2(*(__half2*)&raw.y);
    a.x += f01.x; a.y += f01.y; a.z += f23.x; a.w += f23.y;
}

__device__ __forceinline__ float4 gather_row128(const __half* __restrict__ src,
                                                const int* __restrict__ mem,
                                                int beg, int end, int lane) {
    float4 a = make_float4(0.f, 0.f, 0.f, 0.f);
    int j = beg;
    for (; j + 7 < end; j += 8) {
        int m[8]; uint2 r[8];
#pragma unroll
        for (int k = 0; k < 8; k++) m[k] = mem[j + k];
#pragma unroll
        for (int k = 0; k < 8; k++) r[k] = *(const uint2*)&src[(size_t)m[k] * F1 + lane * 4];
#pragma unroll
        for (int k = 0; k < 8; k++) acc_h4(a, r[k]);
    }
    for (; j + 3 < end; j += 4) {
        int m[4]; uint2 r[4];
#pragma unroll
        for (int k = 0; k < 4; k++) m[k] = mem[j + k];
#pragma unroll
        for (int k = 0; k < 4; k++) r[k] = *(const uint2*)&src[(size_t)m[k] * F1 + lane * 4];
#pragma unroll
        for (int k = 0; k < 4; k++) acc_h4(a, r[k]);
    }
    for (; j < end; j++) {
        uint2 r0 = *(const uint2*)&src[(size_t)mem[j] * F1 + lane * 4];
        acc_h4(a, r0);
    }
    return a;
}

__global__ __launch_bounds__(256) void gather128h(const __half* __restrict__ src,
                                                  __half* __restrict__ dst,
                                                  const int* __restrict__ mem,
                                                  const int* __restrict__ off,
                                                  const float* __restrict__ inv,
                                                  int nrows) {
    int w = (blockIdx.x * blockDim.x + threadIdx.x) >> 5;
    int lane = threadIdx.x & 31;
    if (w >= nrows) return;
    float4 a = gather_row128(src, mem, off[w], off[w + 1], lane);
    float s = inv[w];
    uint2 o;
    *(__half2*)&o.x = __floats2half2_rn(a.x * s, a.y * s);
    *(__half2*)&o.y = __floats2half2_rn(a.z * s, a.w * s);
    *(uint2*)&dst[(size_t)w * F1 + lane * 4] = o;
}

// ------- gather-reduce F=128 + bias + relu + fused [128x16] W2, fp16 hw out -------
__global__ __launch_bounds__(256) void gather128h_w2(const __half* __restrict__ src,
                                                     const int* __restrict__ mem,
                                                     const int* __restrict__ off,
                                                     const float* __restrict__ inv,
                                                     const float* __restrict__ bias,
                                                     const float* __restrict__ W2,
                                                     __half* __restrict__ hw, int nrows) {
    __shared__ float W2s[128][17];
    __shared__ float hs[8][128];
    const int tid = threadIdx.x;
    for (int i = tid; i < 128 * 16; i += 256) W2s[i >> 4][i & 15] = W2[i];
    __syncthreads();

    int w = (blockIdx.x * blockDim.x + tid) >> 5;
    int lane = tid & 31, wl = tid >> 5;
    if (w >= nrows) return;
    float4 a = gather_row128(src, mem, off[w], off[w + 1], lane);
    float s = inv[w];
    float4 b = *(const float4*)&bias[lane * 4];
    hs[wl][lane * 4 + 0] = fmaxf(a.x * s + b.x, 0.f);
    hs[wl][lane * 4 + 1] = fmaxf(a.y * s + b.y, 0.f);
    hs[wl][lane * 4 + 2] = fmaxf(a.z * s + b.z, 0.f);
    hs[wl][lane * 4 + 3] = fmaxf(a.w * s + b.w, 0.f);
    __syncwarp();

    const int c = lane & 15, kh = (lane >> 4) * 64;
    float acc = 0.f;
#pragma unroll 8
    for (int k = 0; k < 64; k++) acc += hs[wl][kh + k] * W2s[kh + k][c];
    acc += __shfl_down_sync(0xffffffffu, acc, 16);
    float part = __shfl_down_sync(0xffffffffu, acc, 1);
    if (lane < 16 && !(lane & 1))
        ((__half2*)hw)[(size_t)w * 8 + (lane >> 1)] = __floats2half2_rn(acc, part);
}

// ---------------- gather-reduce F=16 fp16 (warp per row, 4 members/iter) ----------
template <bool HALF_OUT>
__global__ void gather16h(const __half2* __restrict__ src, void* __restrict__ dst,
                          const int* __restrict__ mem, const int* __restrict__ off,
                          const float* __restrict__ inv, const float* __restrict__ bias,
                          int nrows) {
    int w = (blockIdx.x * blockDim.x + threadIdx.x) >> 5;
    int lane = threadIdx.x & 31;
    if (w >= nrows) return;
    int beg = off[w], end = off[w + 1];
    int g = lane >> 3, f2 = lane & 7;
    float2 acc = make_float2(0.f, 0.f);
    for (int j = beg + g; j < end; j += 4) {
        float2 f = __half22float2(src[(size_t)mem[j] * 8 + f2]);
        acc.x += f.x; acc.y += f.y;
    }
    acc.x += __shfl_down_sync(0xffffffffu, acc.x, 16);
    acc.y += __shfl_down_sync(0xffffffffu, acc.y, 16);
    acc.x += __shfl_down_sync(0xffffffffu, acc.x, 8);
    acc.y += __shfl_down_sync(0xffffffffu, acc.y, 8);
    if (lane < 8) {
        float s = inv[w];
        float rx = acc.x * s, ry = acc.y * s;
        if (bias) { rx += bias[2 * f2]; ry += bias[2 * f2 + 1]; }
        if (HALF_OUT) ((__half2*)dst)[(size_t)w * 8 + f2] = __floats2half2_rn(rx, ry);
        else         ((float2*)dst)[(size_t)w * 8 + f2] = make_float2(rx, ry);
    }
}

// ---------------- launcher ----------------
extern "C" void kernel_launch(void* const* d_in, const int* in_sizes, int n_in,
                              void* d_out, int out_size) {
    const float* x  = (const float*)d_in[0];
    const void*  ni = d_in[1];
    const void*  ei = d_in[2];
    const float* W1 = (const float*)d_in[n_in - 4];
    const float* b1 = (const float*)d_in[n_in - 3];
    const float* W2 = (const float*)d_in[n_in - 2];
    const float* b2 = (const float*)d_in[n_in - 1];
    const int nnz = in_sizes[1];
    const int M   = in_sizes[0] / F1;
    float* out = (float*)d_out;

    static bool  s_init = false;
    static cudaStream_t s2, s3;
    static cudaEvent_t ev_fork, ev_gemm, ev_det, ev_ncsr, ev_fille, ev_tail;
    static int*    p_eoff, *p_noff, *p_emem, *p_nmem;
    static int*    p_ecnt, *p_ncnt, *p_bse, *p_bsn;
    static int*    p_ni32, *p_ei32, *p_rn, *p_re;
    static float*  p_binv, *p_dinv;
    static __half* p_xw, *p_ef, *p_hw, *p_ef2;
    if (!s_init) {
        cudaGetSymbolAddress((void**)&p_eoff, g_eoff);
        cudaGetSymbolAddress((void**)&p_noff, g_noff);
        cudaGetSymbolAddress((void**)&p_emem, g_e_members);
        cudaGetSymbolAddress((void**)&p_nmem, g_n_members);
        cudaGetSymbolAddress((void**)&p_ecnt, g_ecnt);
        cudaGetSymbolAddress((void**)&p_ncnt, g_ncnt);
        cudaGetSymbolAddress((void**)&p_bse,  g_bse);
        cudaGetSymbolAddress((void**)&p_bsn,  g_bsn);
        cudaGetSymbolAddress((void**)&p_ni32, g_ni32);
        cudaGetSymbolAddress((void**)&p_ei32, g_ei32);
        cudaGetSymbolAddress((void**)&p_rn,   g_rank_n);
        cudaGetSymbolAddress((void**)&p_re,   g_rank_e);
        cudaGetSymbolAddress((void**)&p_binv, g_binv);
        cudaGetSymbolAddress((void**)&p_dinv, g_dinv);
        cudaGetSymbolAddress((void**)&p_xw,   g_xw);
        cudaGetSymbolAddress((void**)&p_ef,   g_ef);
        cudaGetSymbolAddress((void**)&p_hw,   g_hw);
        cudaGetSymbolAddress((void**)&p_ef2,  g_ef2);
        cudaStreamCreateWithFlags(&s2, cudaStreamNonBlocking);
        cudaStreamCreateWithFlags(&s3, cudaStreamNonBlocking);
        cudaEventCreateWithFlags(&ev_fork,  cudaEventDisableTiming);
        cudaEventCreateWithFlags(&ev_gemm,  cudaEventDisableTiming);
        cudaEventCreateWithFlags(&ev_det,   cudaEventDisableTiming);
        cudaEventCreateWithFlags(&ev_ncsr,  cudaEventDisableTiming);
        cudaEventCreateWithFlags(&ev_fille, cudaEventDisableTiming);
        cudaEventCreateWithFlags(&ev_tail,  cudaEventDisableTiming);
        s_init = true;
    }

    const int hb4 = (nnz + 1023) / 1024;
    const int blocks_e = (N_EDGES_C * 32 + 255) / 256;
    const int blocks_n = (N_NODES_C * 32 + 255) / 256;

    // ---- fork to s2: W1 split + node-level GEMM (hidden under edge CSR)
    cudaEventRecord(ev_fork, 0);
    cudaStreamWaitEvent(s2, ev_fork, 0);
    split_w1_kernel<<<(F1 * F1 + 255) / 256, 256, 0, s2>>>(W1);
    gemm1_f16<<<(M + 127) / 128, 512, 0, s2>>>(x, p_xw, M);
    cudaEventRecord(ev_gemm, s2);

    // ---- s0: tiny detect (counters zero via static init / prior run's tail)
    detect_kernel<<<1, 64>>>(ni, nnz);
    cudaEventRecord(ev_det, 0);

    // ---- s3: NODE-side CSR (needed only by gather2)
    cudaStreamWaitEvent(s3, ev_det, 0);
    hist_side_kernel<<<hb4, 256, 0, s3>>>(ni, p_ni32, p_rn, p_ncnt, nnz);
    bsums_side_kernel<<<NB_N, 512, 0, s3>>>(p_ncnt, N_NODES_C, p_bsn);
    apply_side_kernel<<<NB_N, 512, 0, s3>>>(p_ncnt, N_NODES_C, p_bsn, p_noff, p_dinv);
    fill_side_kernel<<<hb4, 256, 0, s3>>>(p_ni32, p_rn, p_noff, ei, p_nmem, nnz);
    cudaEventRecord(ev_ncsr, s3);

    // ---- s0: EDGE-side CSR (critical for gather1)
    hist_side_kernel<<<hb4, 256>>>(ei, p_ei32, p_re, p_ecnt, nnz);
    bsums_side_kernel<<<NB_E, 512>>>(p_ecnt, N_EDGES_C, p_bse);
    apply_side_kernel<<<NB_E, 512>>>(p_ecnt, N_EDGES_C, p_bse, p_eoff, p_binv);
    fill_side_kernel<<<hb4, 256>>>(p_ei32, p_re, p_eoff, ni, p_emem, nnz);
    cudaEventRecord(ev_fille, 0);

    // ---- s3 tail: re-zero counters for next run (both applies done by ev_fille:
    // apply_e precedes fill_e on s0; apply_n precedes ev_ncsr which precedes this on s3)
    cudaStreamWaitEvent(s3, ev_fille, 0);
    zero_tail_kernel<<<(N_NODES_C / 4 + 255) / 256, 256, 0, s3>>>();
    cudaEventRecord(ev_tail, s3);

    // ---- joins + gathers
    cudaStreamWaitEvent(0, ev_gemm, 0);   // gather1 needs xw
    gather128h<<<blocks_e, 256>>>(p_xw, p_ef, p_emem, p_eoff, p_binv, N_EDGES_C);

    cudaStreamWaitEvent(0, ev_ncsr, 0);   // gather2 needs node CSR
    gather128h_w2<<<blocks_n, 256>>>(p_ef, p_nmem, p_noff, p_dinv, b1, W2, p_hw, N_NODES_C);

    // layer 2 (fp16 hw/ef2)
    gather16h<true ><<<blocks_e, 256>>>((const __half2*)p_hw,  p_ef2, p_emem, p_eoff,
                                        p_binv, nullptr, N_EDGES_C);
    gather16h<false><<<blocks_n, 256>>>((const __half2*)p_ef2, out,   p_nmem, p_noff,
                                        p_dinv, b2,      N_NODES_C);

    // join s3's tail branch into the origin stream so capture ends fully joined
    // (zero_tail finishes long before the gathers; this edge costs nothing)
    cudaStreamWaitEvent(0, ev_tail, 0);
}

// round 15
// speedup vs baseline: 1.0081x; 1.0081x over previous
#include <cuda_runtime.h>
#include <cuda_fp16.h>

#define N_NODES_C 100000
#define N_EDGES_C 50000
#define NNZ_CAP   1600000
#define F1 128
#define F2 16
#define NB_E ((N_EDGES_C + 511) / 512)   // 98
#define NB_N ((N_NODES_C + 511) / 512)   // 196

// ---------------- static scratch (no cudaMalloc anywhere) ----------------
__device__ int   g_idx64;
__device__ int   g_ncnt[N_NODES_C];      // zero at load; re-zeroed by tail kernel each run
__device__ int   g_ecnt[N_EDGES_C];
__device__ int   g_noff[N_NODES_C + 1];
__device__ int   g_eoff[N_EDGES_C + 1];
__device__ float g_dinv[N_NODES_C];
__device__ float g_binv[N_EDGES_C];
__device__ int   g_ni32[NNZ_CAP];
__device__ int   g_ei32[NNZ_CAP];
__device__ int   g_rank_n[NNZ_CAP];
__device__ int   g_rank_e[NNZ_CAP];
__device__ int   g_e_members[NNZ_CAP];
__device__ int   g_n_members[NNZ_CAP];
__device__ __align__(16) __half g_w1h[F1 * F1];
__device__ __align__(16) __half g_w1l[F1 * F1];
__device__ __align__(16) __half g_xw[(size_t)N_NODES_C * F1];
__device__ __align__(16) __half g_ef[(size_t)N_EDGES_C * F1];
__device__ __align__(16) __half g_hw[(size_t)N_NODES_C * F2];
__device__ __align__(16) __half g_ef2[(size_t)N_EDGES_C * F2];

__device__ __forceinline__ int load_idx(const void* p, int i, int is64) {
    return is64 ? (int)((const long long*)p)[i] : ((const int*)p)[i];
}

// ---------------- tail: re-zero counters for the next run/replay ----------------
__global__ void zero_tail_kernel() {
    int i = blockIdx.x * blockDim.x + threadIdx.x;
    int4 z = make_int4(0, 0, 0, 0);
    if (i < N_NODES_C / 4) ((int4*)g_ncnt)[i] = z;
    if (i < N_EDGES_C / 4) ((int4*)g_ecnt)[i] = z;
}

// ---------------- W1 -> fp16 hi/lo, transposed (s2) ----------------
__global__ void split_w1_kernel(const float* __restrict__ W) {
    int i = blockIdx.x * blockDim.x + threadIdx.x;
    if (i < F1 * F1) {
        int k = i >> 7, n = i & 127;
        float w = W[i];
        __half hi = __float2half_rn(w);
        __half lo = __float2half_rn(w - __half2float(hi));
        g_w1h[n * F1 + k] = hi;
        g_w1l[n * F1 + k] = lo;
    }
}

// ---------------- hist with inline dtype detection, 4 incidences/thread ---------
__global__ void hist_side_kernel(const void* idx, int* __restrict__ idx32,
                                 int* __restrict__ rank, int* __restrict__ cnt, int nnz) {
    // per-block is64 detection: threads 0..63 validate first 64 int64 candidates
    const int tid = threadIdx.x;
    int bad = 0;
    if (tid < 64 && tid < nnz) {
        long long v = ((const long long*)idx)[tid];
        bad = (v < 0 || v >= (1LL << 31)) ? 1 : 0;
    }
    int anybad = __syncthreads_or(bad);
    int is64 = anybad ? 0 : 1;
    if (blockIdx.x == 0 && tid == 0) g_idx64 = is64;   // for fill kernels

    int i0 = (blockIdx.x * blockDim.x + tid) * 4;
    if (i0 >= nnz) return;
    if (i0 + 3 < nnz) {
        int v[4];
        if (is64) {
            longlong2 a = *(const longlong2*)((const long long*)idx + i0);
            longlong2 b = *(const longlong2*)((const long long*)idx + i0 + 2);
            v[0] = (int)a.x; v[1] = (int)a.y; v[2] = (int)b.x; v[3] = (int)b.y;
        } else {
            int4 a = *(const int4*)((const int*)idx + i0);
            v[0] = a.x; v[1] = a.y; v[2] = a.z; v[3] = a.w;
        }
        int r[4];
#pragma unroll
        for (int k = 0; k < 4; k++) r[k] = atomicAdd(&cnt[v[k]], 1);
        *(int4*)(idx32 + i0) = make_int4(v[0], v[1], v[2], v[3]);
        *(int4*)(rank + i0)  = make_int4(r[0], r[1], r[2], r[3]);
    } else {
        for (int k = 0; k < 4 && i0 + k < nnz; k++) {
            int v = load_idx(idx, i0 + k, is64);
            idx32[i0 + k] = v;
            rank[i0 + k]  = atomicAdd(&cnt[v], 1);
        }
    }
}

// ---------------- single-kernel scan+apply: block b recomputes its own base ------
// base = sum(cnt[0 .. 512b)) computed coalesced by all 512 threads; then local
// Hillis-Steele scan over this block's 512 counts; writes off/inv (+off[n]).
__global__ __launch_bounds__(512) void scanapply_side_kernel(const int* __restrict__ cnt,
                                                             int n,
                                                             int* __restrict__ off,
                                                             float* __restrict__ inv) {
    __shared__ int s[512];
    __shared__ int wsum[16];
    __shared__ int base_s;
    const int tid = threadIdx.x, b = blockIdx.x;

    // ---- base: coalesced strided sum over preceding counts
    int lim = b * 512;
    int acc = 0;
    for (int j = tid; j < lim; j += 512) acc += cnt[j];
    for (int d = 16; d > 0; d >>= 1) acc += __shfl_down_sync(0xffffffffu, acc, d);
    if ((tid & 31) == 0) wsum[tid >> 5] = acc;
    __syncthreads();
    if (tid == 0) {
        int t = 0;
#pragma unroll
        for (int i = 0; i < 16; i++) t += wsum[i];
        base_s = t;
    }
    __syncthreads();

    // ---- local inclusive scan of this block's counts
    int i = b * 512 + tid;
    int v = (i < n) ? cnt[i] : 0;
    s[tid] = v;
    __syncthreads();
    for (int d = 1; d < 512; d <<= 1) {
        int t = (tid >= d) ? s[tid - d] : 0;
        __syncthreads();
        s[tid] += t;
        __syncthreads();
    }
    int base = base_s;
    if (i < n) {
        off[i] = base + s[tid] - v;
        inv[i] = v > 0 ? 1.f / (float)v : 0.f;
        if (i == n - 1) off[n] = base + s[tid];
    }
}

// atomic-free fill, 4 per thread
__global__ void fill_side_kernel(const int* __restrict__ idx32, const int* __restrict__ rank,
                                 const int* __restrict__ off, const void* other,
                                 int* __restrict__ members, int nnz) {
    int i0 = (blockIdx.x * blockDim.x + threadIdx.x) * 4;
    if (i0 >= nnz) return;
    int is64 = g_idx64;
    if (i0 + 3 < nnz) {
        int4 id = *(const int4*)(idx32 + i0);
        int4 rk = *(const int4*)(rank + i0);
        int ov[4];
        if (is64) {
            longlong2 a = *(const longlong2*)((const long long*)other + i0);
            longlong2 b = *(const longlong2*)((const long long*)other + i0 + 2);
            ov[0] = (int)a.x; ov[1] = (int)a.y; ov[2] = (int)b.x; ov[3] = (int)b.y;
        } else {
            int4 a = *(const int4*)((const int*)other + i0);
            ov[0] = a.x; ov[1] = a.y; ov[2] = a.z; ov[3] = a.w;
        }
        int o0 = off[id.x], o1 = off[id.y], o2 = off[id.z], o3 = off[id.w];
        members[o0 + rk.x] = ov[0];
        members[o1 + rk.y] = ov[1];
        members[o2 + rk.z] = ov[2];
        members[o3 + rk.w] = ov[3];
    } else {
        for (int k = 0; k < 4 && i0 + k < nnz; k++)
            members[off[idx32[i0 + k]] + rank[i0 + k]] = load_idx(other, i0 + k, is64);
    }
}

// ---------------- node-level GEMM (fp16 2-pass mma) ----------------
__device__ __forceinline__ void mma_f16(float* c, unsigned a0, unsigned a1,
                                        unsigned a2, unsigned a3,
                                        unsigned b0, unsigned b1) {
    asm("mma.sync.aligned.m16n8k16.row.col.f32.f16.f16.f32 "
        "{%0,%1,%2,%3}, {%4,%5,%6,%7}, {%8,%9}, {%0,%1,%2,%3};"
        : "+f"(c[0]), "+f"(c[1]), "+f"(c[2]), "+f"(c[3])
        : "r"(a0), "r"(a1), "r"(a2), "r"(a3), "r"(b0), "r"(b1));
}

__global__ __launch_bounds__(512) void gemm1_f16(const float* __restrict__ A,
                                                 __half* __restrict__ out, int M) {
    __shared__ __half As[128][40];
    __shared__ __half Bh[128][40];
    __shared__ __half Bl[128][40];
    const int tid = threadIdx.x;
    const int wid = tid >> 5, lane = tid & 31;
    const int g = lane >> 2, t = lane & 3;
    const int wm = (wid >> 2) * 32, wn = (wid & 3) * 32;
    const int mbase = blockIdx.x * 128;

    float acc[2][4][4];
#pragma unroll
    for (int a = 0; a < 2; a++)
#pragma unroll
        for (int b = 0; b < 4; b++)
#pragma unroll
            for (int c = 0; c < 4; c++) acc[a][b][c] = 0.f;

    for (int kc = 0; kc < 128; kc += 32) {
#pragma unroll
        for (int i = 0; i < 2; i++) {
            int idx = tid + i * 512;
            int r = idx >> 3, q = idx & 7;
            int row = mbase + r;
            float4 v = (row < M) ? *(const float4*)&A[(size_t)row * 128 + kc + q * 4]
                                 : make_float4(0.f, 0.f, 0.f, 0.f);
            uint2 h;
            *(__half2*)&h.x = __floats2half2_rn(v.x, v.y);
            *(__half2*)&h.y = __floats2half2_rn(v.z, v.w);
            *(uint2*)&As[r][q * 4] = h;
            *(uint2*)&Bh[r][q * 4] = *(const uint2*)&g_w1h[r * 128 + kc + q * 4];
            *(uint2*)&Bl[r][q * 4] = *(const uint2*)&g_w1l[r * 128 + kc + q * 4];
        }
        __syncthreads();

#pragma unroll
        for (int ks = 0; ks < 2; ks++) {
            const int k0 = ks * 16;
#pragma unroll
            for (int mt = 0; mt < 2; mt++) {
                const int rm = wm + mt * 16;
                unsigned a0 = *(unsigned*)&As[rm + g][k0 + 2 * t];
                unsigned a1 = *(unsigned*)&As[rm + g + 8][k0 + 2 * t];
                unsigned a2 = *(unsigned*)&As[rm + g][k0 + 2 * t + 8];
                unsigned a3 = *(unsigned*)&As[rm + g + 8][k0 + 2 * t + 8];
#pragma unroll
                for (int nt = 0; nt < 4; nt++) {
                    int n = wn + nt * 8 + g;
                    unsigned bh0 = *(unsigned*)&Bh[n][k0 + 2 * t];
                    unsigned bh1 = *(unsigned*)&Bh[n][k0 + 2 * t + 8];
                    unsigned bl0 = *(unsigned*)&Bl[n][k0 + 2 * t];
                    unsigned bl1 = *(unsigned*)&Bl[n][k0 + 2 * t + 8];
                    mma_f16(acc[mt][nt], a0, a1, a2, a3, bh0, bh1);
                    mma_f16(acc[mt][nt], a0, a1, a2, a3, bl0, bl1);
                }
            }
        }
        __syncthreads();
    }

#pragma unroll
    for (int mt = 0; mt < 2; mt++) {
#pragma unroll
        for (int nt = 0; nt < 4; nt++) {
            int row = mbase + wm + mt * 16 + g;
            int col = wn + nt * 8 + 2 * t;
            if (row < M)
                *(__half2*)&out[(size_t)row * 128 + col] =
                    __floats2half2_rn(acc[mt][nt][0], acc[mt][nt][1]);
            if (row + 8 < M)
                *(__half2*)&out[(size_t)(row + 8) * 128 + col] =
                    __floats2half2_rn(acc[mt][nt][2], acc[mt][nt][3]);
        }
    }
}

// ---------------- gather-reduce F=128 fp16 (warp per row, 8-deep MLP) -------------
__device__ __forceinline__ void acc_h4(float4& a, uint2 raw) {
    float2 f01 = __half22float2(*(__half2*)&raw.x);
    float2 f23 = __half22float2(*(__half2*)&raw.y);
    a.x += f01.x; a.y += f01.y; a.z += f23.x; a.w += f23.y;
}

__device__ __forceinline__ float4 gather_row128(const __half* __restrict__ src,
                                                const int* __restrict__ mem,
                                                int beg, int end, int lane) {
    float4 a = make_float4(0.f, 0.f, 0.f, 0.f);
    int j = beg;
    for (; j + 7 < end; j += 8) {
        int m[8]; uint2 r[8];
#pragma unroll
        for (int k = 0; k < 8; k++) m[k] = mem[j + k];
#pragma unroll
        for (int k = 0; k < 8; k++) r[k] = *(const uint2*)&src[(size_t)m[k] * F1 + lane * 4];
#pragma unroll
        for (int k = 0; k < 8; k++) acc_h4(a, r[k]);
    }
    for (; j + 3 < end; j += 4) {
        int m[4]; uint2 r[4];
#pragma unroll
        for (int k = 0; k < 4; k++) m[k] = mem[j + k];
#pragma unroll
        for (int k = 0; k < 4; k++) r[k] = *(const uint2*)&src[(size_t)m[k] * F1 + lane * 4];
#pragma unroll
        for (int k = 0; k < 4; k++) acc_h4(a, r[k]);
    }
    for (; j < end; j++) {
        uint2 r0 = *(const uint2*)&src[(size_t)mem[j] * F1 + lane * 4];
        acc_h4(a, r0);
    }
    return a;
}

__global__ __launch_bounds__(256) void gather128h(const __half* __restrict__ src,
                                                  __half* __restrict__ dst,
                                                  const int* __restrict__ mem,
                                                  const int* __restrict__ off,
                                                  const float* __restrict__ inv,
                                                  int nrows) {
    int w = (blockIdx.x * blockDim.x + threadIdx.x) >> 5;
    int lane = threadIdx.x & 31;
    if (w >= nrows) return;
    float4 a = gather_row128(src, mem, off[w], off[w + 1], lane);
    float s = inv[w];
    uint2 o;
    *(__half2*)&o.x = __floats2half2_rn(a.x * s, a.y * s);
    *(__half2*)&o.y = __floats2half2_rn(a.z * s, a.w * s);
    *(uint2*)&dst[(size_t)w * F1 + lane * 4] = o;
}

// ------- gather-reduce F=128 + bias + relu + fused [128x16] W2, fp16 hw out -------
__global__ __launch_bounds__(256) void gather128h_w2(const __half* __restrict__ src,
                                                     const int* __restrict__ mem,
                                                     const int* __restrict__ off,
                                                     const float* __restrict__ inv,
                                                     const float* __restrict__ bias,
                                                     const float* __restrict__ W2,
                                                     __half* __restrict__ hw, int nrows) {
    __shared__ float W2s[128][17];
    __shared__ float hs[8][128];
    const int tid = threadIdx.x;
    for (int i = tid; i < 128 * 16; i += 256) W2s[i >> 4][i & 15] = W2[i];
    __syncthreads();

    int w = (blockIdx.x * blockDim.x + tid) >> 5;
    int lane = tid & 31, wl = tid >> 5;
    if (w >= nrows) return;
    float4 a = gather_row128(src, mem, off[w], off[w + 1], lane);
    float s = inv[w];
    float4 b = *(const float4*)&bias[lane * 4];
    hs[wl][lane * 4 + 0] = fmaxf(a.x * s + b.x, 0.f);
    hs[wl][lane * 4 + 1] = fmaxf(a.y * s + b.y, 0.f);
    hs[wl][lane * 4 + 2] = fmaxf(a.z * s + b.z, 0.f);
    hs[wl][lane * 4 + 3] = fmaxf(a.w * s + b.w, 0.f);
    __syncwarp();

    const int c = lane & 15, kh = (lane >> 4) * 64;
    float acc = 0.f;
#pragma unroll 8
    for (int k = 0; k < 64; k++) acc += hs[wl][kh + k] * W2s[kh + k][c];
    acc += __shfl_down_sync(0xffffffffu, acc, 16);
    float part = __shfl_down_sync(0xffffffffu, acc, 1);
    if (lane < 16 && !(lane & 1))
        ((__half2*)hw)[(size_t)w * 8 + (lane >> 1)] = __floats2half2_rn(acc, part);
}

// ---------------- gather-reduce F=16 fp16 (warp per row, 4 members/iter) ----------
template <bool HALF_OUT>
__global__ void gather16h(const __half2* __restrict__ src, void* __restrict__ dst,
                          const int* __restrict__ mem, const int* __restrict__ off,
                          const float* __restrict__ inv, const float* __restrict__ bias,
                          int nrows) {
    int w = (blockIdx.x * blockDim.x + threadIdx.x) >> 5;
    int lane = threadIdx.x & 31;
    if (w >= nrows) return;
    int beg = off[w], end = off[w + 1];
    int g = lane >> 3, f2 = lane & 7;
    float2 acc = make_float2(0.f, 0.f);
    for (int j = beg + g; j < end; j += 4) {
        float2 f = __half22float2(src[(size_t)mem[j] * 8 + f2]);
        acc.x += f.x; acc.y += f.y;
    }
    acc.x += __shfl_down_sync(0xffffffffu, acc.x, 16);
    acc.y += __shfl_down_sync(0xffffffffu, acc.y, 16);
    acc.x += __shfl_down_sync(0xffffffffu, acc.x, 8);
    acc.y += __shfl_down_sync(0xffffffffu, acc.y, 8);
    if (lane < 8) {
        float s = inv[w];
        float rx = acc.x * s, ry = acc.y * s;
        if (bias) { rx += bias[2 * f2]; ry += bias[2 * f2 + 1]; }
        if (HALF_OUT) ((__half2*)dst)[(size_t)w * 8 + f2] = __floats2half2_rn(rx, ry);
        else         ((float2*)dst)[(size_t)w * 8 + f2] = make_float2(rx, ry);
    }
}

// ---------------- launcher ----------------
extern "C" void kernel_launch(void* const* d_in, const int* in_sizes, int n_in,
                              void* d_out, int out_size) {
    const float* x  = (const float*)d_in[0];
    const void*  ni = d_in[1];
    const void*  ei = d_in[2];
    const float* W1 = (const float*)d_in[n_in - 4];
    const float* b1 = (const float*)d_in[n_in - 3];
    const float* W2 = (const float*)d_in[n_in - 2];
    const float* b2 = (const float*)d_in[n_in - 1];
    const int nnz = in_sizes[1];
    const int M   = in_sizes[0] / F1;
    float* out = (float*)d_out;

    static bool  s_init = false;
    static cudaStream_t s2, s3;
    static cudaEvent_t ev_fork, ev_gemm, ev_fork3, ev_ncsr, ev_fille, ev_tail;
    static int*    p_eoff, *p_noff, *p_emem, *p_nmem;
    static int*    p_ecnt, *p_ncnt;
    static int*    p_ni32, *p_ei32, *p_rn, *p_re;
    static float*  p_binv, *p_dinv;
    static __half* p_xw, *p_ef, *p_hw, *p_ef2;
    if (!s_init) {
        cudaGetSymbolAddress((void**)&p_eoff, g_eoff);
        cudaGetSymbolAddress((void**)&p_noff, g_noff);
        cudaGetSymbolAddress((void**)&p_emem, g_e_members);
        cudaGetSymbolAddress((void**)&p_nmem, g_n_members);
        cudaGetSymbolAddress((void**)&p_ecnt, g_ecnt);
        cudaGetSymbolAddress((void**)&p_ncnt, g_ncnt);
        cudaGetSymbolAddress((void**)&p_ni32, g_ni32);
        cudaGetSymbolAddress((void**)&p_ei32, g_ei32);
        cudaGetSymbolAddress((void**)&p_rn,   g_rank_n);
        cudaGetSymbolAddress((void**)&p_re,   g_rank_e);
        cudaGetSymbolAddress((void**)&p_binv, g_binv);
        cudaGetSymbolAddress((void**)&p_dinv, g_dinv);
        cudaGetSymbolAddress((void**)&p_xw,   g_xw);
        cudaGetSymbolAddress((void**)&p_ef,   g_ef);
        cudaGetSymbolAddress((void**)&p_hw,   g_hw);
        cudaGetSymbolAddress((void**)&p_ef2,  g_ef2);
        cudaStreamCreateWithFlags(&s2, cudaStreamNonBlocking);
        cudaStreamCreateWithFlags(&s3, cudaStreamNonBlocking);
        cudaEventCreateWithFlags(&ev_fork,  cudaEventDisableTiming);
        cudaEventCreateWithFlags(&ev_gemm,  cudaEventDisableTiming);
        cudaEventCreateWithFlags(&ev_fork3, cudaEventDisableTiming);
        cudaEventCreateWithFlags(&ev_ncsr,  cudaEventDisableTiming);
        cudaEventCreateWithFlags(&ev_fille, cudaEventDisableTiming);
        cudaEventCreateWithFlags(&ev_tail,  cudaEventDisableTiming);
        s_init = true;
    }

    const int hb4 = (nnz + 1023) / 1024;
    const int blocks_e = (N_EDGES_C * 32 + 255) / 256;
    const int blocks_n = (N_NODES_C * 32 + 255) / 256;

    // ---- fork to s2: W1 split + node-level GEMM (hidden under edge CSR)
    cudaEventRecord(ev_fork, 0);
    cudaStreamWaitEvent(s2, ev_fork, 0);
    split_w1_kernel<<<(F1 * F1 + 255) / 256, 256, 0, s2>>>(W1);
    gemm1_f16<<<(M + 127) / 128, 512, 0, s2>>>(x, p_xw, M);
    cudaEventRecord(ev_gemm, s2);

    // ---- fork to s3: NODE-side CSR (needed only by gather2)
    cudaEventRecord(ev_fork3, 0);
    cudaStreamWaitEvent(s3, ev_fork3, 0);
    hist_side_kernel<<<hb4, 256, 0, s3>>>(ni, p_ni32, p_rn, p_ncnt, nnz);
    scanapply_side_kernel<<<NB_N, 512, 0, s3>>>(p_ncnt, N_NODES_C, p_noff, p_dinv);
    fill_side_kernel<<<hb4, 256, 0, s3>>>(p_ni32, p_rn, p_noff, ei, p_nmem, nnz);
    cudaEventRecord(ev_ncsr, s3);

    // ---- s0: EDGE-side CSR (critical for gather1) — 3 nodes, no detect
    hist_side_kernel<<<hb4, 256>>>(ei, p_ei32, p_re, p_ecnt, nnz);
    scanapply_side_kernel<<<NB_E, 512>>>(p_ecnt, N_EDGES_C, p_eoff, p_binv);
    fill_side_kernel<<<hb4, 256>>>(p_ei32, p_re, p_eoff, ni, p_emem, nnz);
    cudaEventRecord(ev_fille, 0);

    // ---- s3 tail: re-zero counters for next run (both scanapplies done by ev_fille:
    // scanapply_e precedes fill_e on s0; scanapply_n precedes ev_ncsr on s3)
    cudaStreamWaitEvent(s3, ev_fille, 0);
    zero_tail_kernel<<<(N_NODES_C / 4 + 255) / 256, 256, 0, s3>>>();
    cudaEventRecord(ev_tail, s3);

    // ---- joins + gathers
    cudaStreamWaitEvent(0, ev_gemm, 0);   // gather1 needs xw
    gather128h<<<blocks_e, 256>>>(p_xw, p_ef, p_emem, p_eoff, p_binv, N_EDGES_C);

    cudaStreamWaitEvent(0, ev_ncsr, 0);   // gather2 needs node CSR
    gather128h_w2<<<blocks_n, 256>>>(p_ef, p_nmem, p_noff, p_dinv, b1, W2, p_hw, N_NODES_C);

    // layer 2 (fp16 hw/ef2)
    gather16h<true ><<<blocks_e, 256>>>((const __half2*)p_hw,  p_ef2, p_emem, p_eoff,
                                        p_binv, nullptr, N_EDGES_C);
    gather16h<false><<<blocks_n, 256>>>((const __half2*)p_ef2, out,   p_nmem, p_noff,
                                        p_dinv, b2,      N_NODES_C);

    // join s3's tail branch so capture ends fully joined (costs nothing)
    cudaStreamWaitEvent(0, ev_tail, 0);
}